// round 14
// baseline (speedup 1.0000x reference)
#include <cuda_runtime.h>
#include <cuda_fp16.h>
#include <cstdint>

#define N_ATOMS   65536
#define ATOM_FDIM 133
#define BOND_TOTAL 147
#define BOND_FDIM 14
#define HIDDEN    256
#define MAX_NB    6
#define N_MOLS    2048

#define LDA_AF   160   // 133 -> 160 (5 chunks of 32)
#define LDA_H    256   // 8 chunks of 32
#define N_AF_OUT 512   // [Wi | Wo1] merged

// ---------------- scratch ----------------------------------------------------
__device__ __half g_res[(size_t)N_ATOMS * HIDDEN];
__device__ __half g_P[(size_t)N_ATOMS * HIDDEN];
__device__ __half g_hid[(size_t)N_ATOMS * HIDDEN];
__device__ __half g_Y[(size_t)N_ATOMS * HIDDEN];
__device__ __half g_Af[(size_t)N_ATOMS * LDA_AF];
__device__ __half g_msg[(size_t)N_ATOMS * LDA_H];
__device__ __half g_Waf[(size_t)N_AF_OUT * LDA_AF];
__device__ __half g_Wh1T[(size_t)HIDDEN * LDA_H];
__device__ __half g_Wo2T[(size_t)HIDDEN * LDA_H];

__device__ __forceinline__ uint32_t smem_u32(const void* p) {
    uint32_t a;
    asm("{ .reg .u64 t; cvta.to.shared.u64 t, %1; cvt.u32.u64 %0, t; }" : "=r"(a) : "l"(p));
    return a;
}
__device__ __forceinline__ void cp_async16(uint32_t s, const void* g) {
    asm volatile("cp.async.cg.shared.global [%0], [%1], 16;" :: "r"(s), "l"(g));
}
__device__ __forceinline__ void cp_commit() {
    asm volatile("cp.async.commit_group;" ::: "memory");
}
template <int N>
__device__ __forceinline__ void cp_wait() {
    asm volatile("cp.async.wait_group %0;" :: "n"(N) : "memory");
}
__device__ __forceinline__ void ldm_x4(uint32_t& r0, uint32_t& r1, uint32_t& r2,
                                       uint32_t& r3, uint32_t addr) {
    asm volatile("ldmatrix.sync.aligned.m8n8.x4.shared.b16 {%0,%1,%2,%3}, [%4];"
                 : "=r"(r0), "=r"(r1), "=r"(r2), "=r"(r3) : "r"(addr));
}
__device__ __forceinline__ void mma16816(float* c, const uint32_t* a, const uint32_t* b) {
    asm volatile(
        "mma.sync.aligned.m16n8k16.row.col.f32.f16.f16.f32 "
        "{%0,%1,%2,%3}, {%4,%5,%6,%7}, {%8,%9}, {%0,%1,%2,%3};"
        : "+f"(c[0]), "+f"(c[1]), "+f"(c[2]), "+f"(c[3])
        : "r"(a[0]), "r"(a[1]), "r"(a[2]), "r"(a[3]), "r"(b[0]), "r"(b[1]));
}

// ---------------- merged conversion kernel -----------------------------------
#define NB_AF   (N_ATOMS / 4)
#define NB_WAF  ((N_AF_OUT * LDA_AF + 255) / 256)
#define NB_W    ((HIDDEN * LDA_H + 255) / 256)

__global__ void __launch_bounds__(256)
conv_all_kernel(const float* __restrict__ af,
                const float* __restrict__ Wi, const float* __restrict__ Wh,
                const float* __restrict__ Wo) {
    int b = blockIdx.x;
    int tid = threadIdx.x;
    if (b < NB_AF) {
        int row = b * 4 + (tid >> 6);
        int t = tid & 63;
        const float* src = af + (size_t)row * ATOM_FDIM;
        __half* dst = g_Af + (size_t)row * LDA_AF;
        #pragma unroll
        for (int i = 0; i < 3; i++) {
            int c = t + i * 64;
            if (c < LDA_AF) {
                float v = (c < ATOM_FDIM) ? src[c] : 0.0f;
                dst[c] = __float2half_rn(v);
            }
        }
        return;
    }
    b -= NB_AF;
    if (b < NB_WAF) {
        int idx = b * 256 + tid;
        if (idx < N_AF_OUT * LDA_AF) {
            int n = idx / LDA_AF, k = idx - n * LDA_AF;
            float v = 0.f;
            if (k < ATOM_FDIM)
                v = (n < HIDDEN) ? Wi[(size_t)k * HIDDEN + n]
                                 : Wo[(size_t)k * HIDDEN + (n - HIDDEN)];
            g_Waf[idx] = __float2half_rn(v);
        }
        return;
    }
    b -= NB_WAF;
    if (b < NB_W) {
        int idx = b * 256 + tid;
        int n = idx >> 8, k = idx & 255;
        g_Wh1T[idx] = __float2half_rn(Wh[(size_t)k * HIDDEN + n]);
        return;
    }
    b -= NB_W;
    {
        int idx = b * 256 + tid;
        int n = idx >> 8, k = idx & 255;
        g_Wo2T[idx] = __float2half_rn(Wo[(size_t)(ATOM_FDIM + k) * HIDDEN + n]);
    }
}

// ---------------- bond residual (AFTER gemm0): g_res += bh + nb @ Wh2 --------
__global__ void __launch_bounds__(256)
bond_res_kernel(const int* __restrict__ a2b, const float* __restrict__ f_bonds,
                const float* __restrict__ Wh, const float* __restrict__ bh) {
    __shared__ float W2[BOND_FDIM][HIDDEN];
    __shared__ float nb[4][BOND_FDIM];
    int tid = threadIdx.x;
    for (int i = tid; i < BOND_FDIM * HIDDEN; i += 256)
        W2[i >> 8][i & 255] = Wh[(size_t)(HIDDEN + (i >> 8)) * HIDDEN + (i & 255)];
    int g = tid >> 6, t = tid & 63;
    int atom = blockIdx.x * 4 + g;
    if (t < BOND_FDIM) {
        float s = 0.f;
        #pragma unroll
        for (int j = 0; j < MAX_NB; j++) {
            int b = a2b[atom * MAX_NB + j];
            s += f_bonds[(size_t)b * BOND_TOTAL + (BOND_TOTAL - BOND_FDIM) + t];
        }
        nb[g][t] = s;
    }
    __syncthreads();
    int col = t * 4;
    size_t base = (size_t)atom * HIDDEN + col;
    uint2 ru = *(uint2*)&g_res[base];
    __half2 rp0 = *(__half2*)&ru.x;
    __half2 rp1 = *(__half2*)&ru.y;
    float2 rf0 = __half22float2(rp0), rf1 = __half22float2(rp1);
    float4 r = make_float4(rf0.x, rf0.y, rf1.x, rf1.y);
    float4 bv = *(const float4*)&bh[col];
    r.x += bv.x; r.y += bv.y; r.z += bv.z; r.w += bv.w;
    #pragma unroll
    for (int cc = 0; cc < BOND_FDIM; cc++) {
        float s = nb[g][cc];
        float4 w = *(float4*)&W2[cc][col];
        r.x += s * w.x; r.y += s * w.y; r.z += s * w.z; r.w += s * w.w;
    }
    __half2 h0 = __floats2half2_rn(r.x, r.y);
    __half2 h1 = __floats2half2_rn(r.z, r.w);
    uint2 u; u.x = *(uint32_t*)&h0; u.y = *(uint32_t*)&h1;
    *(uint2*)&g_res[base] = u;
}

// ---------------- gathers ----------------------------------------------------
__device__ __forceinline__ void add_h4(float4& s, const __half* Y, size_t base) {
    uint2 u = *(const uint2*)(Y + base);
    __half2 p0 = *(__half2*)&u.x;
    __half2 p1 = *(__half2*)&u.y;
    float2 f0 = __half22float2(p0), f1 = __half22float2(p1);
    s.x += f0.x; s.y += f0.y; s.z += f1.x; s.w += f1.y;
}

__global__ void gather_relu_kernel(const int* __restrict__ a2a) {
    int atom = blockIdx.x * 4 + (threadIdx.x >> 6);
    int col  = (threadIdx.x & 63) * 4;
    const int2* nb = (const int2*)(a2a + atom * MAX_NB);
    int2 p01 = nb[0], p23 = nb[1], p45 = nb[2];
    const __half* Y = g_Y;
    float4 s = make_float4(0.f, 0.f, 0.f, 0.f);
    add_h4(s, g_res, (size_t)atom * HIDDEN + col);
    add_h4(s, Y, (size_t)p01.x * HIDDEN + col);
    add_h4(s, Y, (size_t)p01.y * HIDDEN + col);
    add_h4(s, Y, (size_t)p23.x * HIDDEN + col);
    add_h4(s, Y, (size_t)p23.y * HIDDEN + col);
    add_h4(s, Y, (size_t)p45.x * HIDDEN + col);
    add_h4(s, Y, (size_t)p45.y * HIDDEN + col);
    __half2 h0 = __floats2half2_rn(fmaxf(s.x, 0.f), fmaxf(s.y, 0.f));
    __half2 h1 = __floats2half2_rn(fmaxf(s.z, 0.f), fmaxf(s.w, 0.f));
    uint2 ph; ph.x = *(uint32_t*)&h0; ph.y = *(uint32_t*)&h1;
    *(uint2*)&g_msg[(size_t)atom * LDA_H + col] = ph;
}

__global__ void gather_final_kernel(const int* __restrict__ a2a,
                                    const float* __restrict__ bo) {
    int atom = blockIdx.x * 4 + (threadIdx.x >> 6);
    int col  = (threadIdx.x & 63) * 4;
    const int2* nb = (const int2*)(a2a + atom * MAX_NB);
    int2 p01 = nb[0], p23 = nb[1], p45 = nb[2];
    const __half* Y = g_Y;
    size_t base = (size_t)atom * HIDDEN + col;
    float4 s = *(const float4*)&bo[col];
    add_h4(s, g_P, base);
    add_h4(s, Y, (size_t)p01.x * HIDDEN + col);
    add_h4(s, Y, (size_t)p01.y * HIDDEN + col);
    add_h4(s, Y, (size_t)p23.x * HIDDEN + col);
    add_h4(s, Y, (size_t)p23.y * HIDDEN + col);
    add_h4(s, Y, (size_t)p45.x * HIDDEN + col);
    add_h4(s, Y, (size_t)p45.y * HIDDEN + col);
    __half2 h0 = __floats2half2_rn(fmaxf(s.x, 0.f), fmaxf(s.y, 0.f));
    __half2 h1 = __floats2half2_rn(fmaxf(s.z, 0.f), fmaxf(s.w, 0.f));
    uint2 u; u.x = *(uint32_t*)&h0; u.y = *(uint32_t*)&h1;
    *(uint2*)&g_hid[base] = u;
}

// ---------------- fp16 GEMM: block tile 256x128, warp tile 64x64, BK=32 -----
#define BK       32
#define ROW_B    80
#define A_TILE_B (256 * ROW_B)    // 20480
#define B_TILE_B (128 * ROW_B)    // 10240
#define STG_B    (A_TILE_B + B_TILE_B)  // 30720
#define SMEM_TOTAL (3 * STG_B)    // 92160

// MODE 0: n0<256:  v = acc+bias (= inp); res = fp16(v); msg = fp16(relu(v)).
//         n0>=256: P = fp16(acc).
// MODE 1: Y = fp16(acc).
template <int MODE>
__global__ void __launch_bounds__(256, 1)
tc_gemm(const __half* __restrict__ Ag, int ldaA,
        const __half* __restrict__ Bg, int ldaB, int chunks,
        const float* __restrict__ bias,
        __half* __restrict__ outRes, __half* __restrict__ outMsg,
        __half* __restrict__ outP, __half* __restrict__ outY)
{
    extern __shared__ char smem[];
    uint32_t sb = smem_u32(smem);
    const int tid  = threadIdx.x;
    const int wid  = tid >> 5;
    const int lane = tid & 31;
    const int row0 = blockIdx.y * 256;
    const int n0   = blockIdx.x * 128;
    const int warp_m = (wid >> 1) * 64;   // 0,64,128,192
    const int warp_n = (wid & 1) * 64;    // 0,64

    float acc[4][8][4];
    #pragma unroll
    for (int i = 0; i < 4; i++)
        #pragma unroll
        for (int j = 0; j < 8; j++)
            #pragma unroll
            for (int q = 0; q < 4; q++) acc[i][j][q] = 0.f;

    auto load_stage = [&](int c, int stg) {
        const int k0 = c * BK;
        const uint32_t sbase = sb + stg * STG_B;
        // A: 256 rows x 64B = 1024 cp16 (4 per thread)
        #pragma unroll
        for (int i = 0; i < 4; i++) {
            int f = i * 256 + tid;
            int r = f >> 2, q = f & 3;
            cp_async16(sbase + (uint32_t)(r * ROW_B + q * 16),
                       Ag + (size_t)(row0 + r) * ldaA + k0 + q * 8);
        }
        // B: 128 rows x 64B = 512 cp16 (2 per thread)
        #pragma unroll
        for (int i = 0; i < 2; i++) {
            int f = i * 256 + tid;
            int r = f >> 2, q = f & 3;
            cp_async16(sbase + A_TILE_B + (uint32_t)(r * ROW_B + q * 16),
                       Bg + (size_t)(n0 + r) * ldaB + k0 + q * 8);
        }
        cp_commit();
    };

    load_stage(0, 0);
    if (chunks > 1) load_stage(1, 1);

    const uint32_t a_row_off = (uint32_t)((warp_m + (lane & 15)) * ROW_B + (lane >> 4) * 16);
    const uint32_t b_row_off = (uint32_t)((warp_n + (lane & 7)) * ROW_B + (lane >> 3) * 16);

    int stg = 0;
    for (int c = 0; c < chunks; c++) {
        if (c == chunks - 1) cp_wait<0>(); else cp_wait<1>();
        __syncthreads();
        if (c + 2 < chunks) {
            int ns = stg + 2; if (ns >= 3) ns -= 3;
            load_stage(c + 2, ns);
        }
        const uint32_t sbase = sb + stg * STG_B;

        uint32_t b[8][4];
        #pragma unroll
        for (int nt = 0; nt < 8; nt++)
            ldm_x4(b[nt][0], b[nt][1], b[nt][2], b[nt][3],
                   sbase + A_TILE_B + b_row_off + (uint32_t)(nt * 8 * ROW_B));
        #pragma unroll
        for (int s = 0; s < 2; s++) {
            const uint32_t koff = (uint32_t)(s * 32);
            #pragma unroll
            for (int mt = 0; mt < 4; mt++) {
                uint32_t a[4];
                ldm_x4(a[0], a[1], a[2], a[3],
                       sbase + a_row_off + (uint32_t)(mt * 16 * ROW_B) + koff);
                #pragma unroll
                for (int nt = 0; nt < 8; nt++) mma16816(acc[mt][nt], a, &b[nt][s * 2]);
            }
        }
        if (++stg == 3) stg = 0;
    }

    // epilogue
    const int rbase = row0 + warp_m + (lane >> 2);
    const int cloc = ((MODE == 0 && n0 >= 256) ? n0 - 256 : n0) + warp_n + (lane & 3) * 2;
    #pragma unroll
    for (int mt = 0; mt < 4; mt++) {
        #pragma unroll
        for (int half_i = 0; half_i < 2; half_i++) {
            const int row = rbase + mt * 16 + half_i * 8;
            const size_t rb = (size_t)row * HIDDEN;
            #pragma unroll
            for (int nt = 0; nt < 8; nt++) {
                const int col = cloc + nt * 8;
                float vx = acc[mt][nt][half_i * 2 + 0];
                float vy = acc[mt][nt][half_i * 2 + 1];
                if (MODE == 1) {
                    *(__half2*)&outY[rb + col] = __floats2half2_rn(vx, vy);
                } else if (n0 < 256) {
                    float2 b = *(const float2*)&bias[col];
                    vx += b.x; vy += b.y;
                    *(__half2*)&outRes[rb + col] = __floats2half2_rn(vx, vy);
                    *(__half2*)&outMsg[rb + col] =
                        __floats2half2_rn(fmaxf(vx, 0.f), fmaxf(vy, 0.f));
                } else {
                    *(__half2*)&outP[rb + col] = __floats2half2_rn(vx, vy);
                }
            }
        }
    }
}

// ---------------- segment mean (binary search over sorted ids) ---------------
__global__ void seg_mean_kernel(const int* __restrict__ seg, float* __restrict__ out) {
    __shared__ int s_lo, s_hi;
    int m = blockIdx.x;
    int c = threadIdx.x;
    if (c == 0) {
        int lo = 0, hi = N_ATOMS;
        while (lo < hi) { int mid = (lo + hi) >> 1; if (seg[mid] < m) lo = mid + 1; else hi = mid; }
        s_lo = lo;
        int lo2 = lo; hi = N_ATOMS;
        while (lo2 < hi) { int mid = (lo2 + hi) >> 1; if (seg[mid] < m + 1) lo2 = mid + 1; else hi = mid; }
        s_hi = lo2;
    }
    __syncthreads();
    int st = s_lo, cnt = s_hi - s_lo;
    float v = 0.f;
    if (cnt > 0) {
        float s = 0.f;
        for (int r = 0; r < cnt; r++)
            s += __half2float(g_hid[(size_t)(st + r) * HIDDEN + c]);
        v = s / (float)cnt;
    }
    out[(size_t)m * HIDDEN + c] = v;
}

// ---------------- launch ------------------------------------------------------
extern "C" void kernel_launch(void* const* d_in, const int* in_sizes, int n_in,
                              void* d_out, int out_size) {
    const float* atom_features = (const float*)d_in[0];
    const float* f_bonds       = (const float*)d_in[1];
    const int*   a2a           = (const int*)d_in[2];
    const int*   a2b           = (const int*)d_in[3];
    const int*   seg           = (const int*)d_in[4];
    const float* Wi            = (const float*)d_in[5];
    const float* bi            = (const float*)d_in[6];
    const float* Wh            = (const float*)d_in[7];
    const float* bh            = (const float*)d_in[8];
    const float* Wo            = (const float*)d_in[9];
    const float* bo            = (const float*)d_in[10];
    float* out = (float*)d_out;

    __half *resp, *Pp, *Yp, *af, *msg, *waf, *wh1, *wo2;
    cudaGetSymbolAddress((void**)&resp, g_res);
    cudaGetSymbolAddress((void**)&Pp, g_P);
    cudaGetSymbolAddress((void**)&Yp, g_Y);
    cudaGetSymbolAddress((void**)&af, g_Af);
    cudaGetSymbolAddress((void**)&msg, g_msg);
    cudaGetSymbolAddress((void**)&waf, g_Waf);
    cudaGetSymbolAddress((void**)&wh1, g_Wh1T);
    cudaGetSymbolAddress((void**)&wo2, g_Wo2T);

    cudaFuncSetAttribute(tc_gemm<0>, cudaFuncAttributeMaxDynamicSharedMemorySize, SMEM_TOTAL);
    cudaFuncSetAttribute(tc_gemm<1>, cudaFuncAttributeMaxDynamicSharedMemorySize, SMEM_TOTAL);

    // 1: merged conversions
    conv_all_kernel<<<NB_AF + NB_WAF + 2 * NB_W, 256>>>(atom_features, Wi, Wh, Wo);

    // 2: merged af GEMM: N=512, K=160.
    dim3 grid_af(N_AF_OUT / 128, N_ATOMS / 256);   // (4, 256)
    tc_gemm<0><<<grid_af, 256, SMEM_TOTAL>>>(af, LDA_AF, waf, LDA_AF, 5,
                                             bi, resp, msg, Pp, nullptr);

    // 3: loop-invariant bond residual: res += bond + bh
    bond_res_kernel<<<N_ATOMS / 4, 256>>>(a2b, f_bonds, Wh, bh);

    dim3 grid_h(HIDDEN / 128, N_ATOMS / 256);      // (2, 256)
    // 4-7: 2 message-passing iterations
    for (int it = 0; it < 2; it++) {
        tc_gemm<1><<<grid_h, 256, SMEM_TOTAL>>>(msg, LDA_H, wh1, LDA_H, 8,
                                                nullptr, nullptr, nullptr, nullptr, Yp);
        gather_relu_kernel<<<N_ATOMS / 4, 256>>>(a2a);
    }

    // 8: Z = msg @ Wo2
    tc_gemm<1><<<grid_h, 256, SMEM_TOTAL>>>(msg, LDA_H, wo2, LDA_H, 8,
                                            nullptr, nullptr, nullptr, nullptr, Yp);

    // 9-10: final gather (atom-parallel) + segment mean
    gather_final_kernel<<<N_ATOMS / 4, 256>>>(a2a, bo);
    seg_mean_kernel<<<N_MOLS, 256>>>(seg, out);
}

// round 15
// speedup vs baseline: 1.1348x; 1.1348x over previous
#include <cuda_runtime.h>
#include <cuda_fp16.h>
#include <cstdint>

#define N_ATOMS   65536
#define ATOM_FDIM 133
#define BOND_TOTAL 147
#define BOND_FDIM 14
#define HIDDEN    256
#define MAX_NB    6
#define N_MOLS    2048

#define LDA_AF   160
#define LDA_H    256
#define N_AF_OUT 512

// ---------------- scratch ----------------------------------------------------
__device__ __half g_res[(size_t)N_ATOMS * HIDDEN];
__device__ __half g_P[(size_t)N_ATOMS * HIDDEN];
__device__ __half g_hid[(size_t)N_ATOMS * HIDDEN];
__device__ __half g_Y[(size_t)N_ATOMS * HIDDEN];
__device__ __half g_Af[(size_t)N_ATOMS * LDA_AF];
__device__ __half g_msg[(size_t)N_ATOMS * LDA_H];
__device__ __half g_Waf[(size_t)N_AF_OUT * LDA_AF];
__device__ __half g_Wh1T[(size_t)HIDDEN * LDA_H];
__device__ __half g_Wo2T[(size_t)HIDDEN * LDA_H];

__device__ __forceinline__ uint32_t smem_u32(const void* p) {
    uint32_t a;
    asm("{ .reg .u64 t; cvta.to.shared.u64 t, %1; cvt.u32.u64 %0, t; }" : "=r"(a) : "l"(p));
    return a;
}
__device__ __forceinline__ void cp_async16(uint32_t s, const void* g) {
    asm volatile("cp.async.cg.shared.global [%0], [%1], 16;" :: "r"(s), "l"(g));
}
__device__ __forceinline__ void cp_commit() {
    asm volatile("cp.async.commit_group;" ::: "memory");
}
template <int N>
__device__ __forceinline__ void cp_wait() {
    asm volatile("cp.async.wait_group %0;" :: "n"(N) : "memory");
}
__device__ __forceinline__ void ldm_x4(uint32_t& r0, uint32_t& r1, uint32_t& r2,
                                       uint32_t& r3, uint32_t addr) {
    asm volatile("ldmatrix.sync.aligned.m8n8.x4.shared.b16 {%0,%1,%2,%3}, [%4];"
                 : "=r"(r0), "=r"(r1), "=r"(r2), "=r"(r3) : "r"(addr));
}
__device__ __forceinline__ void mma16816(float* c, const uint32_t* a, const uint32_t* b) {
    asm volatile(
        "mma.sync.aligned.m16n8k16.row.col.f32.f16.f16.f32 "
        "{%0,%1,%2,%3}, {%4,%5,%6,%7}, {%8,%9}, {%0,%1,%2,%3};"
        : "+f"(c[0]), "+f"(c[1]), "+f"(c[2]), "+f"(c[3])
        : "r"(a[0]), "r"(a[1]), "r"(a[2]), "r"(a[3]), "r"(b[0]), "r"(b[1]));
}

// ---------------- merged conversion kernel -----------------------------------
#define NB_AF   (N_ATOMS / 4)
#define NB_WAF  ((N_AF_OUT * LDA_AF + 255) / 256)
#define NB_W    ((HIDDEN * LDA_H + 255) / 256)

__global__ void __launch_bounds__(256)
conv_all_kernel(const float* __restrict__ af,
                const float* __restrict__ Wi, const float* __restrict__ Wh,
                const float* __restrict__ Wo) {
    int b = blockIdx.x;
    int tid = threadIdx.x;
    if (b < NB_AF) {
        int row = b * 4 + (tid >> 6);
        int t = tid & 63;
        const float* src = af + (size_t)row * ATOM_FDIM;
        __half* dst = g_Af + (size_t)row * LDA_AF;
        #pragma unroll
        for (int i = 0; i < 3; i++) {
            int c = t + i * 64;
            if (c < LDA_AF) {
                float v = (c < ATOM_FDIM) ? src[c] : 0.0f;
                dst[c] = __float2half_rn(v);
            }
        }
        return;
    }
    b -= NB_AF;
    if (b < NB_WAF) {
        int idx = b * 256 + tid;
        if (idx < N_AF_OUT * LDA_AF) {
            int n = idx / LDA_AF, k = idx - n * LDA_AF;
            float v = 0.f;
            if (k < ATOM_FDIM)
                v = (n < HIDDEN) ? Wi[(size_t)k * HIDDEN + n]
                                 : Wo[(size_t)k * HIDDEN + (n - HIDDEN)];
            g_Waf[idx] = __float2half_rn(v);
        }
        return;
    }
    b -= NB_WAF;
    if (b < NB_W) {
        int idx = b * 256 + tid;
        int n = idx >> 8, k = idx & 255;
        g_Wh1T[idx] = __float2half_rn(Wh[(size_t)k * HIDDEN + n]);
        return;
    }
    b -= NB_W;
    {
        int idx = b * 256 + tid;
        int n = idx >> 8, k = idx & 255;
        g_Wo2T[idx] = __float2half_rn(Wo[(size_t)(ATOM_FDIM + k) * HIDDEN + n]);
    }
}

// ---------------- bond residual (AFTER gemm0): g_res += bh + nb @ Wh2 --------
__global__ void __launch_bounds__(256)
bond_res_kernel(const int* __restrict__ a2b, const float* __restrict__ f_bonds,
                const float* __restrict__ Wh, const float* __restrict__ bh) {
    __shared__ float W2[BOND_FDIM][HIDDEN];
    __shared__ float nb[4][BOND_FDIM];
    int tid = threadIdx.x;
    for (int i = tid; i < BOND_FDIM * HIDDEN; i += 256)
        W2[i >> 8][i & 255] = Wh[(size_t)(HIDDEN + (i >> 8)) * HIDDEN + (i & 255)];
    int g = tid >> 6, t = tid & 63;
    int atom = blockIdx.x * 4 + g;
    if (t < BOND_FDIM) {
        float s = 0.f;
        #pragma unroll
        for (int j = 0; j < MAX_NB; j++) {
            int b = a2b[atom * MAX_NB + j];
            s += f_bonds[(size_t)b * BOND_TOTAL + (BOND_TOTAL - BOND_FDIM) + t];
        }
        nb[g][t] = s;
    }
    __syncthreads();
    int col = t * 4;
    size_t base = (size_t)atom * HIDDEN + col;
    uint2 ru = *(uint2*)&g_res[base];
    __half2 rp0 = *(__half2*)&ru.x;
    __half2 rp1 = *(__half2*)&ru.y;
    float2 rf0 = __half22float2(rp0), rf1 = __half22float2(rp1);
    float4 r = make_float4(rf0.x, rf0.y, rf1.x, rf1.y);
    float4 bv = *(const float4*)&bh[col];
    r.x += bv.x; r.y += bv.y; r.z += bv.z; r.w += bv.w;
    #pragma unroll
    for (int cc = 0; cc < BOND_FDIM; cc++) {
        float s = nb[g][cc];
        float4 w = *(float4*)&W2[cc][col];
        r.x += s * w.x; r.y += s * w.y; r.z += s * w.z; r.w += s * w.w;
    }
    __half2 h0 = __floats2half2_rn(r.x, r.y);
    __half2 h1 = __floats2half2_rn(r.z, r.w);
    uint2 u; u.x = *(uint32_t*)&h0; u.y = *(uint32_t*)&h1;
    *(uint2*)&g_res[base] = u;
}

// ---------------- gathers (32 threads/atom, uint4 loads) ---------------------
__device__ __forceinline__ void add_h8(float4& s0, float4& s1,
                                       const __half* Y, size_t base) {
    uint4 u = *(const uint4*)(Y + base);
    float2 f;
    f = __half22float2(*(__half2*)&u.x); s0.x += f.x; s0.y += f.y;
    f = __half22float2(*(__half2*)&u.y); s0.z += f.x; s0.w += f.y;
    f = __half22float2(*(__half2*)&u.z); s1.x += f.x; s1.y += f.y;
    f = __half22float2(*(__half2*)&u.w); s1.z += f.x; s1.w += f.y;
}
__device__ __forceinline__ uint4 pack_relu8(const float4& s0, const float4& s1) {
    __half2 h0 = __floats2half2_rn(fmaxf(s0.x, 0.f), fmaxf(s0.y, 0.f));
    __half2 h1 = __floats2half2_rn(fmaxf(s0.z, 0.f), fmaxf(s0.w, 0.f));
    __half2 h2 = __floats2half2_rn(fmaxf(s1.x, 0.f), fmaxf(s1.y, 0.f));
    __half2 h3 = __floats2half2_rn(fmaxf(s1.z, 0.f), fmaxf(s1.w, 0.f));
    uint4 u;
    u.x = *(uint32_t*)&h0; u.y = *(uint32_t*)&h1;
    u.z = *(uint32_t*)&h2; u.w = *(uint32_t*)&h3;
    return u;
}

// msg = fp16(relu(res + sum_j Y[a2a[i,j]]))   (8 atoms / 256-thr block)
__global__ void gather_relu_kernel(const int* __restrict__ a2a) {
    int atom = blockIdx.x * 8 + (threadIdx.x >> 5);
    int col  = (threadIdx.x & 31) * 8;
    const int2* nb = (const int2*)(a2a + atom * MAX_NB);
    int2 p01 = nb[0], p23 = nb[1], p45 = nb[2];
    const __half* Y = g_Y;
    float4 s0 = make_float4(0.f, 0.f, 0.f, 0.f);
    float4 s1 = make_float4(0.f, 0.f, 0.f, 0.f);
    add_h8(s0, s1, g_res, (size_t)atom * HIDDEN + col);
    add_h8(s0, s1, Y, (size_t)p01.x * HIDDEN + col);
    add_h8(s0, s1, Y, (size_t)p01.y * HIDDEN + col);
    add_h8(s0, s1, Y, (size_t)p23.x * HIDDEN + col);
    add_h8(s0, s1, Y, (size_t)p23.y * HIDDEN + col);
    add_h8(s0, s1, Y, (size_t)p45.x * HIDDEN + col);
    add_h8(s0, s1, Y, (size_t)p45.y * HIDDEN + col);
    *(uint4*)&g_msg[(size_t)atom * LDA_H + col] = pack_relu8(s0, s1);
}

// hid = fp16(relu(P + sum_j Z[a2a[i,j]] + bo))
__global__ void gather_final_kernel(const int* __restrict__ a2a,
                                    const float* __restrict__ bo) {
    int atom = blockIdx.x * 8 + (threadIdx.x >> 5);
    int col  = (threadIdx.x & 31) * 8;
    const int2* nb = (const int2*)(a2a + atom * MAX_NB);
    int2 p01 = nb[0], p23 = nb[1], p45 = nb[2];
    const __half* Y = g_Y;
    size_t base = (size_t)atom * HIDDEN + col;
    float4 s0 = *(const float4*)&bo[col];
    float4 s1 = *(const float4*)&bo[col + 4];
    add_h8(s0, s1, g_P, base);
    add_h8(s0, s1, Y, (size_t)p01.x * HIDDEN + col);
    add_h8(s0, s1, Y, (size_t)p01.y * HIDDEN + col);
    add_h8(s0, s1, Y, (size_t)p23.x * HIDDEN + col);
    add_h8(s0, s1, Y, (size_t)p23.y * HIDDEN + col);
    add_h8(s0, s1, Y, (size_t)p45.x * HIDDEN + col);
    add_h8(s0, s1, Y, (size_t)p45.y * HIDDEN + col);
    *(uint4*)&g_hid[base] = pack_relu8(s0, s1);
}

// ---------------- fp16 GEMM (R13 config: 128x128 block, 64x32 warp, BK=32) --
#define BK       32
#define ROW_B    80
#define TILE_B   (128 * ROW_B)    // 10240
#define STG_B    (2 * TILE_B)     // 20480
#define SMEM_TOTAL (3 * STG_B)    // 61440

template <int MODE>
__global__ void __launch_bounds__(256, 2)
tc_gemm(const __half* __restrict__ Ag, int ldaA,
        const __half* __restrict__ Bg, int ldaB, int chunks,
        const float* __restrict__ bias,
        __half* __restrict__ outRes, __half* __restrict__ outMsg,
        __half* __restrict__ outP, __half* __restrict__ outY)
{
    extern __shared__ char smem[];
    uint32_t sb = smem_u32(smem);
    const int tid  = threadIdx.x;
    const int wid  = tid >> 5;
    const int lane = tid & 31;
    const int row0 = blockIdx.y * 128;
    const int n0   = blockIdx.x * 128;
    const int warp_m = (wid >> 2) * 64;
    const int warp_n = (wid & 3) * 32;

    float acc[4][4][4];
    #pragma unroll
    for (int i = 0; i < 4; i++)
        #pragma unroll
        for (int j = 0; j < 4; j++)
            #pragma unroll
            for (int q = 0; q < 4; q++) acc[i][j][q] = 0.f;

    auto load_stage = [&](int c, int stg) {
        const int k0 = c * BK;
        const uint32_t sbase = sb + stg * STG_B;
        #pragma unroll
        for (int i = 0; i < 2; i++) {
            int f = i * 256 + tid;
            int r = f >> 2, q = f & 3;
            uint32_t so = (uint32_t)(r * ROW_B + q * 16);
            size_t ga = (size_t)(row0 + r) * ldaA + k0 + q * 8;
            size_t gb = (size_t)(n0 + r) * ldaB + k0 + q * 8;
            cp_async16(sbase + 0 * TILE_B + so, Ag + ga);
            cp_async16(sbase + 1 * TILE_B + so, Bg + gb);
        }
        cp_commit();
    };

    load_stage(0, 0);
    if (chunks > 1) load_stage(1, 1);

    const uint32_t a_row_off = (uint32_t)((warp_m + (lane & 15)) * ROW_B + (lane >> 4) * 16);
    const uint32_t b_row_off = (uint32_t)((warp_n + (lane & 7)) * ROW_B + (lane >> 3) * 16);

    int stg = 0;
    for (int c = 0; c < chunks; c++) {
        if (c == chunks - 1) cp_wait<0>(); else cp_wait<1>();
        __syncthreads();
        if (c + 2 < chunks) {
            int ns = stg + 2; if (ns >= 3) ns -= 3;
            load_stage(c + 2, ns);
        }
        const uint32_t sbase = sb + stg * STG_B;

        uint32_t b[4][4];
        #pragma unroll
        for (int nt = 0; nt < 4; nt++)
            ldm_x4(b[nt][0], b[nt][1], b[nt][2], b[nt][3],
                   sbase + 1 * TILE_B + b_row_off + (uint32_t)(nt * 8 * ROW_B));
        #pragma unroll
        for (int s = 0; s < 2; s++) {
            const uint32_t koff = (uint32_t)(s * 32);
            #pragma unroll
            for (int mt = 0; mt < 4; mt++) {
                uint32_t a[4];
                ldm_x4(a[0], a[1], a[2], a[3],
                       sbase + 0 * TILE_B + a_row_off + (uint32_t)(mt * 16 * ROW_B) + koff);
                #pragma unroll
                for (int nt = 0; nt < 4; nt++) mma16816(acc[mt][nt], a, &b[nt][s * 2]);
            }
        }
        if (++stg == 3) stg = 0;
    }

    // epilogue
    const int rbase = row0 + warp_m + (lane >> 2);
    const int cloc = ((MODE == 0 && n0 >= 256) ? n0 - 256 : n0) + warp_n + (lane & 3) * 2;
    #pragma unroll
    for (int mt = 0; mt < 4; mt++) {
        #pragma unroll
        for (int half_i = 0; half_i < 2; half_i++) {
            const int row = rbase + mt * 16 + half_i * 8;
            const size_t rb = (size_t)row * HIDDEN;
            #pragma unroll
            for (int nt = 0; nt < 4; nt++) {
                const int col = cloc + nt * 8;
                float vx = acc[mt][nt][half_i * 2 + 0];
                float vy = acc[mt][nt][half_i * 2 + 1];
                if (MODE == 1) {
                    *(__half2*)&outY[rb + col] = __floats2half2_rn(vx, vy);
                } else if (n0 < 256) {
                    float2 b = *(const float2*)&bias[col];
                    vx += b.x; vy += b.y;
                    *(__half2*)&outRes[rb + col] = __floats2half2_rn(vx, vy);
                    *(__half2*)&outMsg[rb + col] =
                        __floats2half2_rn(fmaxf(vx, 0.f), fmaxf(vy, 0.f));
                } else {
                    *(__half2*)&outP[rb + col] = __floats2half2_rn(vx, vy);
                }
            }
        }
    }
}

// ---------------- segment mean (binary search over sorted ids) ---------------
__global__ void seg_mean_kernel(const int* __restrict__ seg, float* __restrict__ out) {
    __shared__ int s_lo, s_hi;
    int m = blockIdx.x;
    int c = threadIdx.x;
    if (c == 0) {
        int lo = 0, hi = N_ATOMS;
        while (lo < hi) { int mid = (lo + hi) >> 1; if (seg[mid] < m) lo = mid + 1; else hi = mid; }
        s_lo = lo;
        int lo2 = lo; hi = N_ATOMS;
        while (lo2 < hi) { int mid = (lo2 + hi) >> 1; if (seg[mid] < m + 1) lo2 = mid + 1; else hi = mid; }
        s_hi = lo2;
    }
    __syncthreads();
    int st = s_lo, cnt = s_hi - s_lo;
    float v = 0.f;
    if (cnt > 0) {
        float s = 0.f;
        for (int r = 0; r < cnt; r++)
            s += __half2float(g_hid[(size_t)(st + r) * HIDDEN + c]);
        v = s / (float)cnt;
    }
    out[(size_t)m * HIDDEN + c] = v;
}

// ---------------- launch ------------------------------------------------------
extern "C" void kernel_launch(void* const* d_in, const int* in_sizes, int n_in,
                              void* d_out, int out_size) {
    const float* atom_features = (const float*)d_in[0];
    const float* f_bonds       = (const float*)d_in[1];
    const int*   a2a           = (const int*)d_in[2];
    const int*   a2b           = (const int*)d_in[3];
    const int*   seg           = (const int*)d_in[4];
    const float* Wi            = (const float*)d_in[5];
    const float* bi            = (const float*)d_in[6];
    const float* Wh            = (const float*)d_in[7];
    const float* bh            = (const float*)d_in[8];
    const float* Wo            = (const float*)d_in[9];
    const float* bo            = (const float*)d_in[10];
    float* out = (float*)d_out;

    __half *resp, *Pp, *Yp, *af, *msg, *waf, *wh1, *wo2;
    cudaGetSymbolAddress((void**)&resp, g_res);
    cudaGetSymbolAddress((void**)&Pp, g_P);
    cudaGetSymbolAddress((void**)&Yp, g_Y);
    cudaGetSymbolAddress((void**)&af, g_Af);
    cudaGetSymbolAddress((void**)&msg, g_msg);
    cudaGetSymbolAddress((void**)&waf, g_Waf);
    cudaGetSymbolAddress((void**)&wh1, g_Wh1T);
    cudaGetSymbolAddress((void**)&wo2, g_Wo2T);

    cudaFuncSetAttribute(tc_gemm<0>, cudaFuncAttributeMaxDynamicSharedMemorySize, SMEM_TOTAL);
    cudaFuncSetAttribute(tc_gemm<1>, cudaFuncAttributeMaxDynamicSharedMemorySize, SMEM_TOTAL);

    // 1: merged conversions
    conv_all_kernel<<<NB_AF + NB_WAF + 2 * NB_W, 256>>>(atom_features, Wi, Wh, Wo);

    // 2: merged af GEMM: N=512, K=160.
    dim3 grid_af(N_AF_OUT / 128, N_ATOMS / 128);   // (4, 512)
    tc_gemm<0><<<grid_af, 256, SMEM_TOTAL>>>(af, LDA_AF, waf, LDA_AF, 5,
                                             bi, resp, msg, Pp, nullptr);

    // 3: loop-invariant bond residual: res += bond + bh
    bond_res_kernel<<<N_ATOMS / 4, 256>>>(a2b, f_bonds, Wh, bh);

    dim3 grid_h(HIDDEN / 128, N_ATOMS / 128);      // (2, 512)
    // 4-7: 2 message-passing iterations
    for (int it = 0; it < 2; it++) {
        tc_gemm<1><<<grid_h, 256, SMEM_TOTAL>>>(msg, LDA_H, wh1, LDA_H, 8,
                                                nullptr, nullptr, nullptr, nullptr, Yp);
        gather_relu_kernel<<<N_ATOMS / 8, 256>>>(a2a);
    }

    // 8: Z = msg @ Wo2
    tc_gemm<1><<<grid_h, 256, SMEM_TOTAL>>>(msg, LDA_H, wo2, LDA_H, 8,
                                            nullptr, nullptr, nullptr, nullptr, Yp);

    // 9-10: final gather (atom-parallel) + segment mean
    gather_final_kernel<<<N_ATOMS / 8, 256>>>(a2a, bo);
    seg_mean_kernel<<<N_MOLS, 256>>>(seg, out);
}